// round 3
// baseline (speedup 1.0000x reference)
#include <cuda_runtime.h>
#include <cuda_bf16.h>
#include <math.h>

// Problem constants
#define BATCH 32768
#define SNODES 16
#define DIN 128
#define HDIM 64
#define ODIM 32
#define MNODES 16

// Shared memory layout (floats) for main kernel
#define OFF_WT 0          // 64 x 128 transposed W (swizzled)
#define OFF_SF 8192       // 16 batches x 16 rows x 128 (swizzled)
#define OFF_ZS 40960      // 3 x 64 x 32
#define OFF_Y  47104      // 16 groups x 3 x 64
#define OFF_B  50176      // 64 bias
#define SMEM_FLOATS 50240
#define SMEM_BYTES (SMEM_FLOATS * 4)

// Scratch (device globals; no allocation allowed)
__device__ float g_zs[3 * HDIM * ODIM];          // zs per step
__device__ float g_acc[(size_t)BATCH * ODIM];    // pre-BN accumulator (x3)
__device__ float g_p1[256 * ODIM];
__device__ float g_p2[256 * ODIM];
__device__ float g_mean[ODIM];
__device__ float g_scale[ODIM];
__device__ float g_shift[ODIM];

// ---------------------------------------------------------------------------
// Prep: build hidden-graph step matrices zs0/zs1/zs2 (64x32 each).
// zs0[h,o] = sum_m z0[m,h,o]
// zs1[h,o] = sum_m dA[m,o] z0[m,h,o],   dA[q,o] = sum_m A[m,q,o]
// zs2[h,o] = sum_m d2[m,o] z0[m,h,o],   d2[q,o] = sum_p A[p,q,o] dA[p,o]
// ---------------------------------------------------------------------------
__global__ void prep_kernel(const float* __restrict__ adj_hidden,
                            const float* __restrict__ fh) {
    __shared__ float A[MNODES][MNODES][ODIM];   // 32 KB
    __shared__ float dA[MNODES][ODIM];
    __shared__ float d2[MNODES][ODIM];
    int t = threadIdx.x;  // 128 threads

    for (int idx = t; idx < MNODES * MNODES * ODIM; idx += 128)
        ((float*)A)[idx] = 0.f;
    __syncthreads();

    // triu-packed (row-major pairs): decode pair index -> (i,j)
    for (int idx = t; idx < 120 * ODIM; idx += 128) {
        int p = idx >> 5, o = idx & 31;
        int i = 0, rem = p;
        while (rem >= (MNODES - 1 - i)) { rem -= (MNODES - 1 - i); i++; }
        int j = i + 1 + rem;
        float v = fmaxf(adj_hidden[idx], 0.f);
        A[i][j][o] = v;
        A[j][i][o] = v;
    }
    __syncthreads();

    for (int idx = t; idx < MNODES * ODIM; idx += 128) {
        int q = idx >> 5, o = idx & 31;
        float s = 0.f;
        #pragma unroll
        for (int m = 0; m < MNODES; m++) s += A[m][q][o];
        dA[q][o] = s;
    }
    __syncthreads();

    for (int idx = t; idx < MNODES * ODIM; idx += 128) {
        int q = idx >> 5, o = idx & 31;
        float s = 0.f;
        #pragma unroll
        for (int p = 0; p < MNODES; p++) s += A[p][q][o] * dA[p][o];
        d2[q][o] = s;
    }
    __syncthreads();

    for (int idx = t; idx < HDIM * ODIM; idx += 128) {
        int h = idx >> 5, o = idx & 31;
        float s0 = 0.f, s1 = 0.f, s2 = 0.f;
        #pragma unroll
        for (int m = 0; m < MNODES; m++) {
            float z = fh[m * (HDIM * ODIM) + h * ODIM + o];
            s0 += z;
            s1 += dA[m][o] * z;
            s2 += d2[m][o] * z;
        }
        g_zs[idx] = s0;
        g_zs[2048 + idx] = s1;
        g_zs[4096 + idx] = s2;
    }
}

// ---------------------------------------------------------------------------
// Main kernel: per batch b
//   x0[s,h] = sigmoid(features[b,s,:] . W[:,h] + b_in[h])     (the big GEMM)
//   y0[h] = sum_s x0 ; y1[h] = sum_s d[s] x0 ; y2[h] = sum_s e[s] x0
//     d[s] = colsum(adj[b])[s],  e = adj[b]^T d
//   acc[b,o] = sum_{step,h} y_step[h] * zs_step[h,o]
// 16 batches per block, 16 threads per batch, 8x8 register tiles.
// ---------------------------------------------------------------------------
__global__ void __launch_bounds__(256, 1)
main_kernel(const float* __restrict__ adj, const float* __restrict__ feat,
            const float* __restrict__ W, const float* __restrict__ b_in) {
    extern __shared__ float sm[];
    int tid = threadIdx.x;
    int blk = blockIdx.x;

    // Stage W transposed [h][128], XOR-swizzled on 16B granularity by (h>>3)&7
    #pragma unroll 4
    for (int it = 0; it < 32; it++) {
        int idx = it * 256 + tid;
        int h = idx & 63, k = idx >> 6;
        float w = W[k * 64 + h];
        sm[OFF_WT + h * 128 + ((((k >> 2) ^ ((h >> 3) & 7)) << 2) | (k & 3))] = w;
    }
    // Stage features: 16 batches x 16 rows x 128, swizzled by (row>>3)&7
    {
        const float4* src = (const float4*)(feat + (size_t)blk * 16 * SNODES * DIN);
        #pragma unroll 4
        for (int it = 0; it < 32; it++) {
            int idx = it * 256 + tid;          // = r*32 + kq
            int kq = idx & 31, r = idx >> 5;
            float4 v = src[idx];
            *(float4*)&sm[OFF_SF + r * 128 + ((kq ^ ((r >> 3) & 7)) << 2)] = v;
        }
    }
    for (int idx = tid; idx < 6144; idx += 256) sm[OFF_ZS + idx] = g_zs[idx];
    if (tid < 64) sm[OFF_B + tid] = b_in[tid];
    __syncthreads();

    int g = tid >> 4, tg = tid & 15;
    int b = blk * 16 + g;
    int lane = tid & 31;
    int s_base = (tg >> 3) << 3;   // 0 or 8
    int h_base = (tg & 7) << 3;    // 0..56

    // Degree weights from adj (column sums; adj symmetric so == row sums)
    const float* adjb = adj + (size_t)b * (SNODES * SNODES);
    float dsum = 0.f;
    #pragma unroll
    for (int s = 0; s < 16; s++) dsum += adjb[s * 16 + tg];
    float esum = 0.f;
    #pragma unroll
    for (int u = 0; u < 16; u++) {
        float du = __shfl_sync(0xffffffffu, dsum, (lane & 16) | u);
        esum += adjb[u * 16 + tg] * du;
    }
    float w1v[8], w2v[8];
    #pragma unroll
    for (int i = 0; i < 8; i++) {
        w1v[i] = __shfl_sync(0xffffffffu, dsum, (lane & 16) | (s_base + i));
        w2v[i] = __shfl_sync(0xffffffffu, esum, (lane & 16) | (s_base + i));
    }

    // GEMM: 8 s-rows x 8 h-cols per thread over k=128
    float acc[8][8];
    #pragma unroll
    for (int i = 0; i < 8; i++)
        #pragma unroll
        for (int j = 0; j < 8; j++) acc[i][j] = 0.f;

    const float* fbase = sm + OFF_SF + (g * 16 + s_base) * 128;
    const float* wbase = sm + OFF_WT + h_base * 128;
    int fsw = ((g * 16 + s_base) >> 3) & 7;
    int wsw = tg & 7;

    #pragma unroll 1
    for (int kq = 0; kq < 32; kq++) {
        float4 fv[8], wv[8];
        int kf = (kq ^ fsw) << 2;
        int kw = (kq ^ wsw) << 2;
        #pragma unroll
        for (int i = 0; i < 8; i++)
            fv[i] = *(const float4*)(fbase + i * 128 + kf);
        #pragma unroll
        for (int j = 0; j < 8; j++)
            wv[j] = *(const float4*)(wbase + j * 128 + kw);
        #pragma unroll
        for (int i = 0; i < 8; i++)
            #pragma unroll
            for (int j = 0; j < 8; j++) {
                acc[i][j] += fv[i].x * wv[j].x;
                acc[i][j] += fv[i].y * wv[j].y;
                acc[i][j] += fv[i].z * wv[j].z;
                acc[i][j] += fv[i].w * wv[j].w;
            }
    }

    // Epilogue: bias + sigmoid + weighted node sums
    float y0[8], y1[8], y2[8];
    #pragma unroll
    for (int j = 0; j < 8; j++) { y0[j] = 0.f; y1[j] = 0.f; y2[j] = 0.f; }
    #pragma unroll
    for (int i = 0; i < 8; i++)
        #pragma unroll
        for (int j = 0; j < 8; j++) {
            float v = acc[i][j] + sm[OFF_B + h_base + j];
            v = 1.f / (1.f + __expf(-v));
            y0[j] += v;
            y1[j] += w1v[i] * v;
            y2[j] += w2v[i] * v;
        }
    // reduce over the two s-halves (partner lane = lane ^ 8, same group)
    #pragma unroll
    for (int j = 0; j < 8; j++) {
        y0[j] += __shfl_xor_sync(0xffffffffu, y0[j], 8);
        y1[j] += __shfl_xor_sync(0xffffffffu, y1[j], 8);
        y2[j] += __shfl_xor_sync(0xffffffffu, y2[j], 8);
    }
    if (tg < 8) {
        float* yp = sm + OFF_Y + g * 192;
        #pragma unroll
        for (int j = 0; j < 8; j++) {
            yp[h_base + j] = y0[j];
            yp[64 + h_base + j] = y1[j];
            yp[128 + h_base + j] = y2[j];
        }
    }
    __syncwarp();

    // Contraction with zs: 2 outputs per thread
    float a1 = 0.f, a2 = 0.f;
    const float* yp = sm + OFF_Y + g * 192;
    #pragma unroll 1
    for (int st = 0; st < 3; st++) {
        #pragma unroll 8
        for (int h = 0; h < 64; h++) {
            float yv = yp[st * 64 + h];
            a1 += yv * sm[OFF_ZS + st * 2048 + h * 32 + tg];
            a2 += yv * sm[OFF_ZS + st * 2048 + h * 32 + tg + 16];
        }
    }
    g_acc[(size_t)b * 32 + tg] = a1;
    g_acc[(size_t)b * 32 + tg + 16] = a2;
}

// ---------------------------------------------------------------------------
// Deterministic two-stage reductions for BatchNorm stats (two-pass variance)
// ---------------------------------------------------------------------------
__global__ void red1_kernel() {
    __shared__ float s[256];
    int t = threadIdx.x, blk = blockIdx.x;
    int o = t & 31, rg = t >> 5;
    float local = 0.f;
    int base = blk * 128;
    #pragma unroll
    for (int j = 0; j < 16; j++)
        local += g_acc[(size_t)(base + rg + j * 8) * 32 + o];
    s[t] = local;
    __syncthreads();
    if (t < 32) {
        float tot = 0.f;
        #pragma unroll
        for (int j = 0; j < 8; j++) tot += s[j * 32 + t];
        g_p1[blk * 32 + t] = tot;
    }
}

__global__ void red1b_kernel() {
    __shared__ float s[256];
    int t = threadIdx.x;
    int o = t & 31, rg = t >> 5;
    float local = 0.f;
    #pragma unroll
    for (int j = 0; j < 32; j++) local += g_p1[(rg + j * 8) * 32 + o];
    s[t] = local;
    __syncthreads();
    if (t < 32) {
        float tot = 0.f;
        #pragma unroll
        for (int j = 0; j < 8; j++) tot += s[j * 32 + t];
        g_mean[t] = tot * (1.f / (3.f * (float)BATCH));
    }
}

__global__ void red2_kernel() {
    __shared__ float s[256];
    int t = threadIdx.x, blk = blockIdx.x;
    int o = t & 31, rg = t >> 5;
    float mu = g_mean[o];
    float local = 0.f;
    int base = blk * 128;
    #pragma unroll
    for (int j = 0; j < 16; j++) {
        float v = g_acc[(size_t)(base + rg + j * 8) * 32 + o] * (1.f / 3.f) - mu;
        local += v * v;
    }
    s[t] = local;
    __syncthreads();
    if (t < 32) {
        float tot = 0.f;
        #pragma unroll
        for (int j = 0; j < 8; j++) tot += s[j * 32 + t];
        g_p2[blk * 32 + t] = tot;
    }
}

__global__ void red2b_kernel(const float* __restrict__ gamma,
                             const float* __restrict__ beta) {
    __shared__ float s[256];
    int t = threadIdx.x;
    int o = t & 31, rg = t >> 5;
    float local = 0.f;
    #pragma unroll
    for (int j = 0; j < 32; j++) local += g_p2[(rg + j * 8) * 32 + o];
    s[t] = local;
    __syncthreads();
    if (t < 32) {
        float tot = 0.f;
        #pragma unroll
        for (int j = 0; j < 8; j++) tot += s[j * 32 + t];
        float var = tot * (1.f / (float)BATCH);
        float istd = rsqrtf(var + 1e-5f);
        float sc = gamma[t] * istd;
        g_scale[t] = sc;
        g_shift[t] = beta[t] - g_mean[t] * sc;
    }
}

__global__ void fin_kernel(float* __restrict__ out) {
    int idx = blockIdx.x * 256 + threadIdx.x;   // float4 index, 262144 total
    float4 a = ((const float4*)g_acc)[idx];
    int o0 = (idx & 7) << 2;
    float4 r;
    {
        float v = a.x * (1.f / 3.f) * g_scale[o0 + 0] + g_shift[o0 + 0];
        r.x = 1.f / (1.f + __expf(-v));
    }
    {
        float v = a.y * (1.f / 3.f) * g_scale[o0 + 1] + g_shift[o0 + 1];
        r.y = 1.f / (1.f + __expf(-v));
    }
    {
        float v = a.z * (1.f / 3.f) * g_scale[o0 + 2] + g_shift[o0 + 2];
        r.z = 1.f / (1.f + __expf(-v));
    }
    {
        float v = a.w * (1.f / 3.f) * g_scale[o0 + 3] + g_shift[o0 + 3];
        r.w = 1.f / (1.f + __expf(-v));
    }
    ((float4*)out)[idx] = r;
}

// ---------------------------------------------------------------------------
extern "C" void kernel_launch(void* const* d_in, const int* in_sizes, int n_in,
                              void* d_out, int out_size) {
    const float* adj   = (const float*)d_in[0];
    const float* feat  = (const float*)d_in[1];
    const float* W     = (const float*)d_in[2];
    const float* b_in  = (const float*)d_in[3];
    const float* fh    = (const float*)d_in[4];
    const float* ah    = (const float*)d_in[5];
    const float* gamma = (const float*)d_in[6];
    const float* beta  = (const float*)d_in[7];
    float* out = (float*)d_out;

    cudaFuncSetAttribute(main_kernel,
                         cudaFuncAttributeMaxDynamicSharedMemorySize, SMEM_BYTES);

    prep_kernel<<<1, 128>>>(ah, fh);
    main_kernel<<<BATCH / 16, 256, SMEM_BYTES>>>(adj, feat, W, b_in);
    red1_kernel<<<256, 256>>>();
    red1b_kernel<<<1, 256>>>();
    red2_kernel<<<256, 256>>>();
    red2b_kernel<<<1, 256>>>(gamma, beta);
    fin_kernel<<<1024, 256>>>(out);
}